// round 5
// baseline (speedup 1.0000x reference)
#include <cuda_runtime.h>
#include <cuda_bf16.h>
#include <mma.h>

using namespace nvcuda;

#define N_ 8192
#define D_ 128
#define NLAB 10
#define SCALE 0.08838834764831845f   // 1/sqrt(128)
#define EPS 1e-8f

// ---------------- scratch (device globals: allocation-free) ----------------
static __device__ float         g_E[(size_t)N_ * N_];   // exp(p)  (256 MB)
static __device__ __nv_bfloat16 g_U[(size_t)N_ * N_];   // ab      (128 MB)
static __device__ __nv_bfloat16 g_V[(size_t)N_ * N_];   // ba^T    (128 MB)
static __device__ float g_rsumInv[N_];
static __device__ float g_csumInv[N_];
static __device__ float g_vp[N_];          // column sums of U
static __device__ int   g_cnt[NLAB];
static __device__ int   g_startL[NLAB + 1];
static __device__ int   g_idx[N_];
static __device__ int   g_tilesL[NLAB];
static __device__ int   g_tileStart[NLAB + 1];
static __device__ int   g_numTiles;
static __device__ int   g_isI64;
static __device__ float g_walkerAcc;

// Label fetch that tolerates both int32 and int64 buffers.
__device__ __forceinline__ int get_label(const void* L, int i, int isI64) {
    int v = isI64 ? (int)((const long long*)L)[i] : ((const int*)L)[i];
    return min(max(v, 0), NLAB - 1);
}

// ---------------- 1) P = a b^T * scale; store E = exp(P) ----------------
__global__ __launch_bounds__(256) void gemm_p_kernel(const float* __restrict__ A,
                                                     const float* __restrict__ B) {
    __shared__ float As[32][65];
    __shared__ float Bs[32][65];
    int tid = threadIdx.x;
    int tx = tid & 15, ty = tid >> 4;
    int bi = blockIdx.y * 64, bj = blockIdx.x * 64;
    float acc[4][4] = {};
    for (int k0 = 0; k0 < D_; k0 += 32) {
        #pragma unroll
        for (int q = 0; q < 8; q++) {
            int l = tid + q * 256;
            int r = l >> 5, k = l & 31;
            As[k][r] = A[(size_t)(bi + r) * D_ + k0 + k];
            Bs[k][r] = B[(size_t)(bj + r) * D_ + k0 + k];
        }
        __syncthreads();
        #pragma unroll
        for (int k = 0; k < 32; k++) {
            float ra[4], rb[4];
            #pragma unroll
            for (int i = 0; i < 4; i++) ra[i] = As[k][ty * 4 + i];
            #pragma unroll
            for (int j = 0; j < 4; j++) rb[j] = Bs[k][tx * 4 + j];
            #pragma unroll
            for (int i = 0; i < 4; i++)
                #pragma unroll
                for (int j = 0; j < 4; j++) acc[i][j] += ra[i] * rb[j];
        }
        __syncthreads();
    }
    #pragma unroll
    for (int i = 0; i < 4; i++) {
        size_t rowoff = (size_t)(bi + ty * 4 + i) * N_ + bj + tx * 4;
        #pragma unroll
        for (int j = 0; j < 4; j++)
            g_E[rowoff + j] = __expf(acc[i][j] * SCALE);
    }
}

// ---------------- 2) row sums of E ----------------
__global__ __launch_bounds__(256) void row_sum_kernel() {
    __shared__ float red[8];
    int row = blockIdx.x, tid = threadIdx.x;
    const float* p = &g_E[(size_t)row * N_];
    float s = 0.f;
    for (int c = tid; c < N_; c += 256) s += p[c];
    #pragma unroll
    for (int o = 16; o; o >>= 1) s += __shfl_xor_sync(~0u, s, o);
    if ((tid & 31) == 0) red[tid >> 5] = s;
    __syncthreads();
    if (tid == 0) {
        float t = 0.f;
        for (int w = 0; w < 8; w++) t += red[w];
        g_rsumInv[row] = 1.f / t;
    }
}

// ---------------- 3) col sums of E ----------------
__global__ __launch_bounds__(256) void col_sum_kernel() {
    __shared__ float sm[256];
    int tid = threadIdx.x;
    int c0 = blockIdx.x * 32;
    int col = tid & 31, grp = tid >> 5;
    float s = 0.f;
    for (int r = grp; r < N_; r += 8) s += g_E[(size_t)r * N_ + c0 + col];
    sm[tid] = s;
    __syncthreads();
    if (tid < 32) {
        float t = 0.f;
        #pragma unroll
        for (int g = 0; g < 8; g++) t += sm[tid + 32 * g];
        g_csumInv[c0 + tid] = 1.f / t;
    }
}

// ---------------- 4) U, V (bf16) and visit column sums ----------------
__global__ __launch_bounds__(256) void uv_vp_kernel() {
    __shared__ float sm[256];
    int tid = threadIdx.x;
    int c0 = blockIdx.x * 32;
    int col = tid & 31, grp = tid >> 5;
    int c = c0 + col;
    float ci = g_csumInv[c];
    float vpacc = 0.f;
    for (int r = grp; r < N_; r += 8) {
        size_t o = (size_t)r * N_ + c;
        float e = g_E[o];
        float u = e * g_rsumInv[r];
        float v = e * ci;
        g_U[o] = __float2bfloat16(u);
        g_V[o] = __float2bfloat16(v);
        vpacc += u;
    }
    sm[tid] = vpacc;
    __syncthreads();
    if (tid < 32) {
        float t = 0.f;
        #pragma unroll
        for (int g = 0; g < 8; g++) t += sm[tid + 32 * g];
        g_vp[c0 + tid] = t;
    }
}

// ---------------- 5) dtype probe + label histogram + tile bookkeeping ----------------
__global__ __launch_bounds__(256) void prep1_kernel(const void* __restrict__ labels) {
    __shared__ int scnt[NLAB];
    __shared__ int oddNonzero;
    int tid = threadIdx.x;
    if (tid < NLAB) scnt[tid] = 0;
    if (tid == 0) oddNonzero = 0;
    __syncthreads();

    // Probe dtype: read first 8192 int32 words (safe for both int32[8192] and
    // int64[8192] buffers). int64 little-endian with values 0..9 => every
    // odd-indexed word is 0.
    {
        const int* w = (const int*)labels;
        int local = 0;
        for (int i = tid; i < N_ / 2; i += 256)
            if (w[2 * i + 1] != 0) local = 1;
        if (local) oddNonzero = 1;   // benign race, all writers store 1
    }
    __syncthreads();
    int isI64 = !oddNonzero;
    if (tid == 0) g_isI64 = isI64;

    for (int i = tid; i < N_; i += 256)
        atomicAdd(&scnt[get_label(labels, i, isI64)], 1);
    __syncthreads();
    if (tid == 0) {
        int st = 0, ts = 0;
        for (int l = 0; l < NLAB; l++) {
            int cnum = scnt[l];
            g_cnt[l] = cnum;
            g_startL[l] = st; st += cnum;
            int tl = (cnum + 63) >> 6;
            g_tilesL[l] = tl;
            g_tileStart[l] = ts; ts += tl * tl;
        }
        g_startL[NLAB] = st;
        g_tileStart[NLAB] = ts;
        g_numTiles = ts;
        g_walkerAcc = 0.f;
    }
}

// ---------------- 6) deterministic stable scatter of indices by label ----------------
__global__ __launch_bounds__(256) void prep2_kernel(const void* __restrict__ labels) {
    __shared__ unsigned char slab[N_];
    int tid = threadIdx.x;
    int isI64 = g_isI64;
    for (int i = tid; i < N_; i += 256)
        slab[i] = (unsigned char)get_label(labels, i, isI64);
    __syncthreads();
    int i = blockIdx.x * 256 + tid;
    unsigned char lab = slab[i];
    int pos = 0;
    for (int q = 0; q < i; q++) pos += (slab[q] == lab);
    g_idx[g_startL[lab] + pos] = i;
}

// ---------------- 7) label-sparse aba GEMM (bf16 wmma, K=8192) + log reduce ----------------
__global__ __launch_bounds__(256) void walker_kernel() {
    __shared__ __align__(32) __nv_bfloat16 Us[64 * 72];
    __shared__ __align__(32) __nv_bfloat16 Vs[64 * 72];
    __shared__ __align__(32) float Cs[64 * 64];
    __shared__ int Ridx[64], Cidx[64];
    __shared__ float red[8];

    int tid = threadIdx.x;
    int warp = tid >> 5, lane = tid & 31;
    int ci = warp & 3, ri = warp >> 2;   // warp computes tiles (ri,ci) and (ri+2,ci)
    int numTiles = g_numTiles;
    float blockAcc = 0.f;

    for (int t = blockIdx.x; t < numTiles; t += gridDim.x) {
        int L = 0;
        while (t >= g_tileStart[L + 1]) L++;
        int local = t - g_tileStart[L];
        int tl = g_tilesL[L];
        int nL = g_cnt[L];
        int base = g_startL[L];
        int ti = local / tl, tj = local % tl;

        if (tid < 64) {
            int r = ti * 64 + tid;
            Ridx[tid] = (r < nL) ? g_idx[base + r] : -1;
            int c = tj * 64 + tid;
            Cidx[tid] = (c < nL) ? g_idx[base + c] : -1;
        }
        wmma::fragment<wmma::accumulator, 16, 16, 16, float> c0, c1;
        wmma::fill_fragment(c0, 0.f);
        wmma::fill_fragment(c1, 0.f);
        __syncthreads();

        for (int k0 = 0; k0 < N_; k0 += 64) {
            #pragma unroll
            for (int q = 0; q < 2; q++) {
                int e = tid * 2 + q;
                int r = e >> 3, kk = (e & 7) * 8;
                uint4 z = make_uint4(0, 0, 0, 0);
                int gi = Ridx[r];
                uint4 vu = z;
                if (gi >= 0) vu = *(const uint4*)&g_U[(size_t)gi * N_ + k0 + kk];
                *(uint4*)&Us[r * 72 + kk] = vu;
                int gj = Cidx[r];
                uint4 vv = z;
                if (gj >= 0) vv = *(const uint4*)&g_V[(size_t)gj * N_ + k0 + kk];
                *(uint4*)&Vs[r * 72 + kk] = vv;
            }
            __syncthreads();
            #pragma unroll
            for (int ks = 0; ks < 4; ks++) {
                wmma::fragment<wmma::matrix_a, 16, 16, 16, __nv_bfloat16, wmma::row_major> a0, a1;
                wmma::fragment<wmma::matrix_b, 16, 16, 16, __nv_bfloat16, wmma::col_major> b;
                wmma::load_matrix_sync(b, &Vs[ci * 16 * 72 + ks * 16], 72);
                wmma::load_matrix_sync(a0, &Us[ri * 16 * 72 + ks * 16], 72);
                wmma::mma_sync(c0, a0, b, c0);
                wmma::load_matrix_sync(a1, &Us[(ri + 2) * 16 * 72 + ks * 16], 72);
                wmma::mma_sync(c1, a1, b, c1);
            }
            __syncthreads();
        }
        wmma::store_matrix_sync(&Cs[ri * 16 * 64 + ci * 16], c0, 64, wmma::mem_row_major);
        wmma::store_matrix_sync(&Cs[(ri + 2) * 16 * 64 + ci * 16], c1, 64, wmma::mem_row_major);
        __syncthreads();

        int rlim = nL - ti * 64;   // entries beyond are padded-zero rows/cols
        int clim = nL - tj * 64;
        float s = 0.f;
        #pragma unroll
        for (int q = 0; q < 16; q++) {
            int e = tid + q * 256;
            int r = e >> 6, c = e & 63;
            if (r < rlim && c < clim) s += logf(EPS + Cs[e]);
        }
        #pragma unroll
        for (int o = 16; o; o >>= 1) s += __shfl_xor_sync(~0u, s, o);
        if (lane == 0) red[warp] = s;
        __syncthreads();
        if (tid == 0) {
            float ts = 0.f;
            for (int w = 0; w < 8; w++) ts += red[w];
            blockAcc += ts / (float)nL;   // targets weight 1/cnt_L
        }
        __syncthreads();
    }
    if (tid == 0) atomicAdd(&g_walkerAcc, blockAcc);
}

// ---------------- 8) visit loss + outputs ----------------
__global__ __launch_bounds__(256) void finalize_kernel(float* __restrict__ out) {
    __shared__ float red[8];
    int tid = threadIdx.x;
    float s = 0.f;
    for (int m = tid; m < N_; m += 256)
        s += logf(EPS + g_vp[m] * (1.0f / N_));
    #pragma unroll
    for (int o = 16; o; o >>= 1) s += __shfl_xor_sync(~0u, s, o);
    if ((tid & 31) == 0) red[tid >> 5] = s;
    __syncthreads();
    if (tid == 0) {
        float t = 0.f;
        for (int w = 0; w < 8; w++) t += red[w];
        out[1] = -t * (1.0f / N_);              // visit_loss (uniform = 1/M)
        out[0] = -g_walkerAcc * (1.0f / N_);    // walker_loss (mean over rows)
    }
}

// ---------------- launch ----------------
extern "C" void kernel_launch(void* const* d_in, const int* in_sizes, int n_in,
                              void* d_out, int out_size) {
    const float* a = (const float*)d_in[0];
    const float* b = (const float*)d_in[1];
    const void* labels = d_in[2];
    float* out = (float*)d_out;

    dim3 gp(128, 128);
    gemm_p_kernel<<<gp, 256>>>(a, b);
    row_sum_kernel<<<N_, 256>>>();
    col_sum_kernel<<<256, 256>>>();
    uv_vp_kernel<<<256, 256>>>();
    prep1_kernel<<<1, 256>>>(labels);
    prep2_kernel<<<32, 256>>>(labels);
    walker_kernel<<<2048, 256>>>();
    finalize_kernel<<<1, 256>>>(out);
}